// round 7
// baseline (speedup 1.0000x reference)
#include <cuda_runtime.h>
#include <cooperative_groups.h>

namespace cg = cooperative_groups;

#define NN    5000
#define MM    10
#define SR    11        // smem row stride (conflict-free, gcd(11,32)=1)
#define NT    16
#define FF    128
#define NFW   3
#define NSINK 10
#define NC    8
#define RPC   (NN/NC)   // 625
#define TPB   512
#define NWARP (TPB/32)
#define WS    160
#define EMAX  80000

// ---------------- device scratch ----------------
__device__ unsigned int g_bitmap[NN * WS];     // zero-initialized; k_fill re-clears
__device__ int   g_deg[NN];
__device__ int   g_rowptr[NN + 1];
__device__ int   g_cols[EMAX];
__device__ float g_Y[(size_t)NT * NN * MM];

// ---------------- preprocessing ----------------
__global__ void k_mark(const int* __restrict__ ei, int E) {
    int e = blockIdx.x * blockDim.x + threadIdx.x;
    if (e >= E) return;
    int s = ei[e], d = ei[E + e];
    atomicOr(&g_bitmap[s * WS + (d >> 5)], 1u << (d & 31));
}

__global__ void k_deg() {
    int w    = (blockIdx.x * blockDim.x + threadIdx.x) >> 5;
    int lane = threadIdx.x & 31;
    if (w >= NN) return;
    const uint4* bp = reinterpret_cast<const uint4*>(g_bitmap + (size_t)w * WS);
    uint4 a = bp[lane];
    int c = __popc(a.x) + __popc(a.y) + __popc(a.z) + __popc(a.w);
    if (lane < 8) {
        uint4 b = bp[32 + lane];
        c += __popc(b.x) + __popc(b.y) + __popc(b.z) + __popc(b.w);
    }
    #pragma unroll
    for (int o = 16; o; o >>= 1) c += __shfl_xor_sync(0xffffffffu, c, o);
    if (lane == 0) g_deg[w] = c;
}

__global__ void k_scan() {
    __shared__ int wsum[32];
    int tid = threadIdx.x, lane = tid & 31, w = tid >> 5;
    int base = tid * 5, loc[5], s = 0;
    #pragma unroll
    for (int k = 0; k < 5; k++) {
        int v = (base + k < NN) ? g_deg[base + k] : 0;
        loc[k] = v; s += v;
    }
    int inc = s;
    #pragma unroll
    for (int o = 1; o < 32; o <<= 1) {
        int v = __shfl_up_sync(0xffffffffu, inc, o);
        if (lane >= o) inc += v;
    }
    if (lane == 31) wsum[w] = inc;
    __syncthreads();
    if (w == 0) {
        int v2 = wsum[lane], i2 = v2;
        #pragma unroll
        for (int o = 1; o < 32; o <<= 1) {
            int t = __shfl_up_sync(0xffffffffu, i2, o);
            if (lane >= o) i2 += t;
        }
        wsum[lane] = i2 - v2;   // exclusive warp offsets
    }
    __syncthreads();
    int excl = wsum[w] + inc - s;
    #pragma unroll
    for (int k = 0; k < 5; k++) {
        if (base + k < NN) { g_rowptr[base + k] = excl; excl += loc[k]; }
    }
    if (tid == 1023) g_rowptr[NN] = excl;
}

// emit sorted CSR cols AND clear the bitmap (so every call sees clean state)
__global__ void k_fill() {
    int w    = (blockIdx.x * blockDim.x + threadIdx.x) >> 5;
    int lane = threadIdx.x & 31;
    if (w >= NN) return;
    unsigned int* bp = g_bitmap + (size_t)w * WS;
    unsigned int wd[5];
    int c = 0;
    #pragma unroll
    for (int k = 0; k < 5; k++) {
        wd[k] = bp[lane * 5 + k];
        bp[lane * 5 + k] = 0u;
        c += __popc(wd[k]);
    }
    int inc = c;
    #pragma unroll
    for (int o = 1; o < 32; o <<= 1) {
        int v = __shfl_up_sync(0xffffffffu, inc, o);
        if (lane >= o) inc += v;
    }
    int pos = g_rowptr[w] + inc - c;
    #pragma unroll
    for (int k = 0; k < 5; k++) {
        unsigned int x = wd[k];
        int bb = (lane * 5 + k) * 32;
        while (x) {
            int b = __ffs(x) - 1;
            g_cols[pos++] = bb + b;
            x &= x - 1;
        }
    }
}

// ---------------- main kernel ----------------
struct Smem {
    alignas(16) float Pub[2][NC][16];   // [buf][srcRank][slot]
    alignas(16) float Partial[16];
    alignas(8)  unsigned long long bar;
    float Scal[4];                      // [0]=reg [1]=cmin [2]=gamma
    float Wred[NWARP][16];
    float q[MM], qC2[MM], cc[MM], fsq[MM], V[MM];
    float C2[MM * MM];
    alignas(16) float F2[MM * FF];
    float DegN[RPC], U[RPC];
    float M[RPC * SR], K[RPC * SR], T[RPC * SR], ATC[RPC * SR], AdT[RPC * SR];
};

__device__ __forceinline__ unsigned su32(const void* p) {
    unsigned r;
    asm("{ .reg .u64 t; cvta.to.shared.u64 t, %1; cvt.u32.u64 %0, t; }"
        : "=r"(r) : "l"(p));
    return r;
}

// all-to-all scalar exchange: Partial[0..15] -> Pub[buf][myrank][*] on all 8
// CTAs; 8 arrivals per local mbarrier; tid<16 wait (acquire.cluster).
// Returns the buffer index holding this exchange's data.
__device__ __forceinline__ int cexchange(Smem* s, cg::cluster_group& cl,
                                         int tid, int myrank, int& ph) {
    unsigned bar = su32(&s->bar);
    int buf = ph;
    __syncwarp();   // Partial (tid<16) -> writers (tid<8), same warp
    if (tid < 8) {
        float* lp = &s->Pub[buf][myrank][0];
        float4* dst = reinterpret_cast<float4*>(cl.map_shared_rank(lp, tid));
        const float4* src = reinterpret_cast<const float4*>(&s->Partial[0]);
        dst[0] = src[0]; dst[1] = src[1]; dst[2] = src[2]; dst[3] = src[3];
        asm volatile(
            "{\n\t.reg .b32 ra;\n\t"
            "mapa.shared::cluster.u32 ra, %0, %1;\n\t"
            "mbarrier.arrive.release.cluster.shared::cluster.b64 _, [ra];\n\t}"
            :: "r"(bar), "r"(tid) : "memory");
    }
    if (tid < 16) {
        asm volatile(
            "{\n\t.reg .pred P1;\n\t"
            "WL_%=:\n\t"
            "mbarrier.try_wait.parity.acquire.cluster.shared::cta.b64 P1, [%0], %1, 0x989680;\n\t"
            "@P1 bra.uni WD_%=;\n\t"
            "bra.uni WL_%=;\n\t"
            "WD_%=:\n\t}"
            :: "r"(bar), "r"(ph) : "memory");
    }
    ph ^= 1;
    return buf;
}

__global__ void __launch_bounds__(TPB, 1) __cluster_dims__(NC, 1, 1)
k_main(const float* __restrict__ x,
       const float* __restrict__ tA,
       const float* __restrict__ tF,
       const float* __restrict__ q0,
       const float* __restrict__ a0,
       float* __restrict__ out)
{
    extern __shared__ char smem_raw[];
    Smem* s = reinterpret_cast<Smem*>(smem_raw);
    cg::cluster_group cluster = cg::this_cluster();
    const int rank = (int)cluster.block_rank();
    const int tpl  = blockIdx.x / NC;
    const int tid  = threadIdx.x;
    const int wid  = tid >> 5, lane = tid & 31;
    const int r0   = rank * RPC;
    const float P  = 1.0f / (float)NN;
    const float alpha = 1.0f / (1.0f + expf(-a0[0]));
    const float oma = 1.0f - alpha, ta = 2.0f * alpha;
    float* Yt = g_Y + (size_t)tpl * NN * MM;
    int ph = 0;

    // ---- phase 0 ----
    if (tid == 0)
        asm volatile("mbarrier.init.shared.b64 [%0], %1;"
                     :: "r"(su32(&s->bar)), "r"(NC) : "memory");
    for (int i = tid; i < MM * FF; i += TPB) s->F2[i] = tF[(size_t)tpl * MM * FF + i];
    if (tid < MM * MM) s->C2[tid] = tA[tpl * MM * MM + tid];
    if (tid == 0) {
        float qq[MM], mx = -1e30f;
        #pragma unroll
        for (int k = 0; k < MM; k++) { qq[k] = q0[tpl * MM + k]; mx = fmaxf(mx, qq[k]); }
        float ssum = 0.f;
        #pragma unroll
        for (int k = 0; k < MM; k++) { qq[k] = expf(qq[k] - mx); ssum += qq[k]; }
        #pragma unroll
        for (int k = 0; k < MM; k++) s->q[k] = qq[k] / ssum;
    }
    __syncthreads();
    if (tid < MM) {
        int j = tid;
        float a1 = 0.f, a2 = 0.f, a3 = 0.f;
        #pragma unroll
        for (int k = 0; k < MM; k++) {
            a1 += s->q[k] * s->C2[k * MM + j];
            float cj = s->C2[j * MM + k];
            a2 += cj * cj * s->q[k];
        }
        for (int c = 0; c < FF; c++) { float fv = s->F2[j * FF + c]; a3 += fv * fv; }
        s->qC2[j] = a1; s->cc[j] = a2; s->fsq[j] = a3;
    }
    __syncthreads();

    // ---- phase 1: M, DegN, T0, ATC0 ----
    for (int r = wid; r < RPC; r += NWARP) {
        int gi = r0 + r;
        const float* xr = x + (size_t)gi * FF;
        float acc[MM];
        #pragma unroll
        for (int j = 0; j < MM; j++) acc[j] = 0.f;
        float xs = 0.f;
        #pragma unroll
        for (int c = 0; c < FF / 32; c++) {
            float xv = xr[c * 32 + lane];
            xs += xv * xv;
            #pragma unroll
            for (int j = 0; j < MM; j++) acc[j] += xv * s->F2[j * FF + c * 32 + lane];
        }
        #pragma unroll
        for (int o = 16; o; o >>= 1) {
            xs += __shfl_xor_sync(0xffffffffu, xs, o);
            #pragma unroll
            for (int j = 0; j < MM; j++) acc[j] += __shfl_xor_sync(0xffffffffu, acc[j], o);
        }
        float dn = (float)g_deg[gi] * P;
        if (lane == 0) s->DegN[r] = dn;
        if (lane < MM) {
            int j = lane;
            s->M[r * SR + j]   = xs + s->fsq[j] - 2.f * acc[j];
            s->T[r * SR + j]   = P * s->q[j];
            s->ATC[r * SR + j] = dn * s->qC2[j];
        }
    }
    cluster.sync();   // mbarrier init visible cluster-wide before first exchange

    // ---- Frank-Wolfe ----
    for (int fw = 0; fw < NFW; fw++) {
        // (a) G; stats sum|G|, min G
        float psum = 0.f, pmin = 1e30f;
        for (int li = tid; li < RPC; li += TPB) {
            float dn = s->DegN[li];
            #pragma unroll
            for (int j = 0; j < MM; j++) {
                int e = li * SR + j;
                float g = oma * s->M[e] + ta * (dn + s->cc[j] - 2.f * s->ATC[e]);
                s->K[e] = g;
                psum += fabsf(g);
                pmin = fminf(pmin, g);
            }
        }
        #pragma unroll
        for (int o = 16; o; o >>= 1) {
            psum += __shfl_xor_sync(0xffffffffu, psum, o);
            pmin = fminf(pmin, __shfl_xor_sync(0xffffffffu, pmin, o));
        }
        if (lane == 0) { s->Wred[wid][0] = psum; s->Wred[wid][1] = pmin; }
        __syncthreads();
        if (tid == 0) {
            float bs = 0.f;
            for (int w = 0; w < NWARP; w++) bs += s->Wred[w][0];
            s->Partial[0] = bs;
        } else if (tid == 1) {
            float bm = 1e30f;
            for (int w = 0; w < NWARP; w++) bm = fminf(bm, s->Wred[w][1]);
            s->Partial[1] = bm;
        }
        {
            int b = cexchange(s, cluster, tid, rank, ph);
            if (tid == 0) {
                float bs = 0.f, bm = 1e30f;
                for (int r = 0; r < NC; r++) {
                    bs += s->Pub[b][r][0];
                    bm = fminf(bm, s->Pub[b][r][1]);
                }
                s->Scal[0] = 0.05f * (bs / (float)(NN * MM)) + 1e-9f;
                s->Scal[1] = bm;
            }
        }
        if (tid < MM) s->V[tid] = 1.f;
        __syncthreads();

        // (b) K = exp(-(G - cmin)/reg)
        {
            float inv = 1.0f / s->Scal[0], cmin = s->Scal[1];
            for (int li = tid; li < RPC; li += TPB) {
                #pragma unroll
                for (int j = 0; j < MM; j++) {
                    int e = li * SR + j;
                    s->K[e] = expf(fmaxf((cmin - s->K[e]) * inv, -80.f));
                }
            }
        }

        // (c) Sinkhorn
        for (int it = 0; it < NSINK; it++) {
            float vr[MM];
            #pragma unroll
            for (int j = 0; j < MM; j++) vr[j] = s->V[j];
            float col[MM];
            #pragma unroll
            for (int j = 0; j < MM; j++) col[j] = 0.f;
            for (int li = tid; li < RPC; li += TPB) {
                float kr[MM];
                #pragma unroll
                for (int j = 0; j < MM; j++) kr[j] = s->K[li * SR + j];
                float kv = 0.f;
                #pragma unroll
                for (int j = 0; j < MM; j++) kv += kr[j] * vr[j];
                float u = P / kv;
                s->U[li] = u;
                #pragma unroll
                for (int j = 0; j < MM; j++) col[j] += kr[j] * u;
            }
            #pragma unroll
            for (int o = 16; o; o >>= 1) {
                #pragma unroll
                for (int j = 0; j < MM; j++) col[j] += __shfl_xor_sync(0xffffffffu, col[j], o);
            }
            if (lane == 0) {
                #pragma unroll
                for (int j = 0; j < MM; j++) s->Wred[wid][j] = col[j];
            }
            __syncthreads();
            if (tid < MM) {
                float t = 0.f;
                for (int w = 0; w < NWARP; w++) t += s->Wred[w][tid];
                s->Partial[tid] = t;
            }
            int b = cexchange(s, cluster, tid, rank, ph);
            if (tid < MM) {
                float tot = 0.f;
                for (int r = 0; r < NC; r++) tot += s->Pub[b][r][tid];
                s->V[tid] = s->q[tid] / tot;
            }
            __syncthreads();
        }

        // (d) dT; stage Y=dT@C2 in AdT smem; publish to global; partial dots
        float pM = 0.f, pC = 0.f, pA = 0.f, pa = 0.f;
        {
            float vr[MM];
            #pragma unroll
            for (int j = 0; j < MM; j++) vr[j] = s->V[j];
            for (int li = tid; li < RPC; li += TPB) {
                float u = s->U[li];
                float d[MM];
                #pragma unroll
                for (int j = 0; j < MM; j++) {
                    int e = li * SR + j;
                    d[j] = u * s->K[e] * vr[j] - s->T[e];
                }
                float dn = s->DegN[li];
                #pragma unroll
                for (int j = 0; j < MM; j++) {
                    int e = li * SR + j;
                    pM += s->M[e] * d[j];
                    pC += (dn + s->cc[j]) * d[j];
                    pA += s->ATC[e] * d[j];
                }
                #pragma unroll
                for (int jj = 0; jj < MM; jj++) {
                    float y = 0.f;
                    #pragma unroll
                    for (int j = 0; j < MM; j++) y += d[j] * s->C2[j * MM + jj];
                    s->AdT[li * SR + jj] = y;
                }
            }
        }
        __syncthreads();
        for (int idx = tid; idx < RPC * MM; idx += TPB) {
            int r = idx / MM, j = idx - r * MM;
            Yt[(size_t)(r0 + r) * MM + j] = s->AdT[r * SR + j];
        }
        __threadfence();
        cluster.sync();

        // (e) SpMM gather: warp-per-row, lane=(neighbor,col) mapping
        {
            const int sub = lane / 10;
            const int jj  = lane - sub * 10;     // lane % 10
            const bool act = lane < 30;
            for (int r = wid; r < RPC; r += NWARP) {
                int gi = r0 + r;
                int rb = g_rowptr[gi], re = g_rowptr[gi + 1];
                float acc = 0.f;
                for (int base = rb; base < re; base += 30) {
                    int nav = min(30, re - base);
                    int myc = (lane < nav) ? g_cols[base + lane] : 0;
                    for (int k = 0; k < nav; k += 3) {
                        int c = __shfl_sync(0xffffffffu, myc, k + sub);
                        if (act && (k + sub) < nav)
                            acc += __ldg(&Yt[(size_t)c * MM + jj]);
                    }
                }
                float a1 = __shfl_down_sync(0xffffffffu, acc, 10);
                float a2 = __shfl_down_sync(0xffffffffu, acc, 20);
                if (lane < 10) {
                    float a = acc + a1 + a2;
                    int e = r * SR + lane;
                    s->AdT[e] = a;
                    float d = s->U[r] * s->K[e] * s->V[lane] - s->T[e];
                    pa += a * d;
                }
            }
        }

        // (f) reduce (pa,pM,pC,pA); gamma
        #pragma unroll
        for (int o = 16; o; o >>= 1) {
            pa += __shfl_xor_sync(0xffffffffu, pa, o);
            pM += __shfl_xor_sync(0xffffffffu, pM, o);
            pC += __shfl_xor_sync(0xffffffffu, pC, o);
            pA += __shfl_xor_sync(0xffffffffu, pA, o);
        }
        if (lane == 0) {
            s->Wred[wid][0] = pa; s->Wred[wid][1] = pM;
            s->Wred[wid][2] = pC; s->Wred[wid][3] = pA;
        }
        __syncthreads();
        if (tid < 4) {
            float t = 0.f;
            for (int w = 0; w < NWARP; w++) t += s->Wred[w][tid];
            s->Partial[tid] = t;
        }
        {
            int b = cexchange(s, cluster, tid, rank, ph);
            if (tid == 0) {
                float Ta = 0, Tm = 0, Tc = 0, TA = 0;
                for (int r = 0; r < NC; r++) {
                    Ta += s->Pub[b][r][0]; Tm += s->Pub[b][r][1];
                    Tc += s->Pub[b][r][2]; TA += s->Pub[b][r][3];
                }
                float a = -2.f * alpha * Ta;
                float bb = oma * Tm + alpha * (Tc - 4.f * TA);
                float gam;
                if (a > 0.f) {
                    gam = -bb / (2.f * a + 1e-16f);
                    gam = fminf(fmaxf(gam, 0.f), 1.f);
                } else {
                    gam = (a + bb < 0.f) ? 1.f : 0.f;
                }
                s->Scal[2] = gam;
            }
        }
        __syncthreads();

        // (g) T += gam*dT; ATC += gam*AdTC
        {
            float gam = s->Scal[2];
            float vr[MM];
            #pragma unroll
            for (int j = 0; j < MM; j++) vr[j] = s->V[j];
            for (int li = tid; li < RPC; li += TPB) {
                float u = s->U[li];
                #pragma unroll
                for (int j = 0; j < MM; j++) {
                    int e = li * SR + j;
                    float d = u * s->K[e] * vr[j] - s->T[e];
                    s->T[e]   += gam * d;
                    s->ATC[e] += gam * s->AdT[e];
                }
            }
        }
        __syncthreads();
    }

    // ---- final distance ----
    float pd = 0.f;
    for (int li = tid; li < RPC; li += TPB) {
        float dn = s->DegN[li];
        #pragma unroll
        for (int j = 0; j < MM; j++) {
            int e = li * SR + j;
            float t = s->T[e];
            pd += oma * s->M[e] * t + alpha * ((dn + s->cc[j]) * t - 2.f * s->ATC[e] * t);
        }
    }
    #pragma unroll
    for (int o = 16; o; o >>= 1) pd += __shfl_xor_sync(0xffffffffu, pd, o);
    if (lane == 0) s->Wred[wid][0] = pd;
    __syncthreads();
    if (tid == 0) {
        float bs = 0.f;
        for (int w = 0; w < NWARP; w++) bs += s->Wred[w][0];
        s->Partial[0] = bs;
    }
    {
        int b = cexchange(s, cluster, tid, rank, ph);
        if (rank == 0 && tid == 0) {
            float tot = 0.f;
            for (int r = 0; r < NC; r++) tot += s->Pub[b][r][0];
            out[tpl] = tot;
        }
    }
    cluster.sync();   // keep CTAs alive until all exchange traffic fully drained
}

// ---------------- launch ----------------
extern "C" void kernel_launch(void* const* d_in, const int* in_sizes, int n_in,
                              void* d_out, int out_size)
{
    const float* x  = (const float*)d_in[0];
    const int*   ei = (const int*)  d_in[1];
    const float* tA = (const float*)d_in[2];
    const float* tF = (const float*)d_in[3];
    const float* q0 = (const float*)d_in[4];
    const float* a0 = (const float*)d_in[5];
    float* out = (float*)d_out;
    int E = in_sizes[1] / 2;

    cudaFuncSetAttribute(k_main, cudaFuncAttributeMaxDynamicSharedMemorySize,
                         (int)sizeof(Smem));

    k_mark<<<(E + 255) / 256, 256>>>(ei, E);
    k_deg<<<(NN * 32 + 255) / 256, 256>>>();
    k_scan<<<1, 1024>>>();
    k_fill<<<(NN * 32 + 255) / 256, 256>>>();
    k_main<<<NT * NC, TPB, sizeof(Smem)>>>(x, tA, tF, q0, a0, out);
}

// round 8
// speedup vs baseline: 1.7970x; 1.7970x over previous
#include <cuda_runtime.h>
#include <cooperative_groups.h>

namespace cg = cooperative_groups;

// Problem constants (fixed shapes)
#define NN    5000      // graph nodes
#define MM    10        // template nodes
#define SR    11        // smem row stride (gcd(11,32)=1 -> conflict-free)
#define NT    16        // templates
#define FF    128       // features
#define NFW   3         // Frank-Wolfe iters
#define NSINK 10        // Sinkhorn iters
#define NC    8         // CTAs per cluster (per template)
#define RPC   (NN/NC)   // rows per CTA = 625
#define TPB   512
#define NWARP (TPB/32)
#define WS    160       // bitmap words per row (157 used, padded)
#define EMAX  80000

// ---------------- device scratch (static; no allocation) ----------------
__device__ unsigned int g_bitmap[NN * WS];       // zero-init; k_fill leaves it clean
__device__ int   g_deg[NN];
__device__ int   g_rowptr[NN + 1];
__device__ int   g_cols[EMAX];
__device__ float g_Y[(size_t)NT * NN * MM];      // dT@C2 per template

// ---------------- preprocessing kernels ----------------
__global__ void k_mark(const int* __restrict__ ei, int E) {
    int e = blockIdx.x * blockDim.x + threadIdx.x;
    if (e >= E) return;
    int s = ei[e];
    int d = ei[E + e];
    atomicOr(&g_bitmap[s * WS + (d >> 5)], 1u << (d & 31));
}

// one warp per row: deduped degree via popcount
__global__ void k_deg() {
    int w    = (blockIdx.x * blockDim.x + threadIdx.x) >> 5;
    int lane = threadIdx.x & 31;
    if (w >= NN) return;
    const unsigned int* bp = g_bitmap + (size_t)w * WS;
    int c = 0;
    #pragma unroll
    for (int k = 0; k < 5; k++) c += __popc(bp[lane * 5 + k]);
    #pragma unroll
    for (int o = 16; o; o >>= 1) c += __shfl_xor_sync(0xffffffffu, c, o);
    if (lane == 0) g_deg[w] = c;
}

// single-block exclusive scan of g_deg -> g_rowptr (warp-shuffle version)
__global__ void k_scan() {
    __shared__ int wsum[32];
    int tid = threadIdx.x, lane = tid & 31, w = tid >> 5;
    int base = tid * 5, loc[5], s = 0;
    #pragma unroll
    for (int k = 0; k < 5; k++) {
        int v = (base + k < NN) ? g_deg[base + k] : 0;
        loc[k] = v; s += v;
    }
    int inc = s;
    #pragma unroll
    for (int o = 1; o < 32; o <<= 1) {
        int v = __shfl_up_sync(0xffffffffu, inc, o);
        if (lane >= o) inc += v;
    }
    if (lane == 31) wsum[w] = inc;
    __syncthreads();
    if (w == 0) {
        int v2 = wsum[lane], i2 = v2;
        #pragma unroll
        for (int o = 1; o < 32; o <<= 1) {
            int t = __shfl_up_sync(0xffffffffu, i2, o);
            if (lane >= o) i2 += t;
        }
        wsum[lane] = i2 - v2;   // exclusive warp offsets
    }
    __syncthreads();
    int excl = wsum[w] + inc - s;
    #pragma unroll
    for (int k = 0; k < 5; k++) {
        if (base + k < NN) { g_rowptr[base + k] = excl; excl += loc[k]; }
    }
    if (tid == 1023) g_rowptr[NN] = excl;
}

// one warp per row: emit sorted column indices (deterministic CSR) AND clear bitmap
__global__ void k_fill() {
    int w    = (blockIdx.x * blockDim.x + threadIdx.x) >> 5;
    int lane = threadIdx.x & 31;
    if (w >= NN) return;
    unsigned int* bp = g_bitmap + (size_t)w * WS;
    unsigned int wd[5];
    int c = 0;
    #pragma unroll
    for (int k = 0; k < 5; k++) {
        wd[k] = bp[lane * 5 + k];
        bp[lane * 5 + k] = 0u;
        c += __popc(wd[k]);
    }
    int inc = c;
    #pragma unroll
    for (int o = 1; o < 32; o <<= 1) {
        int v = __shfl_up_sync(0xffffffffu, inc, o);
        if (lane >= o) inc += v;
    }
    int pos = g_rowptr[w] + inc - c;
    #pragma unroll
    for (int k = 0; k < 5; k++) {
        unsigned int x = wd[k];
        int bb = (lane * 5 + k) * 32;
        while (x) {
            int b = __ffs(x) - 1;
            g_cols[pos++] = bb + b;
            x &= x - 1;
        }
    }
}

// ---------------- main FGW kernel: one 8-CTA cluster per template ----------------
struct __align__(16) Smem {
    float M[RPC * SR];
    float K[RPC * SR];      // holds G, then K = exp(-(G-c)/reg)
    float T[RPC * SR];
    float ATC[RPC * SR];
    float AdT[RPC * SR];
    float DegN[RPC];        // deg_i / N
    float U[RPC];
    float F2[MM * FF];
    float C2[MM * MM];
    float q[MM], qC2[MM], cc[MM], fsq[MM];
    float V[MM];
    float Pub[2][16];       // double-buffered cluster exchange
    float Wred[NWARP][16];  // block-reduction scratch
    float Scal[4];          // [0]=reg [1]=cmin [2]=gamma
};

__global__ void __launch_bounds__(TPB, 1) __cluster_dims__(NC, 1, 1)
k_main(const float* __restrict__ x,
       const float* __restrict__ tA,
       const float* __restrict__ tF,
       const float* __restrict__ q0,
       const float* __restrict__ a0,
       float* __restrict__ out)
{
    extern __shared__ char smem_raw[];
    Smem* s = reinterpret_cast<Smem*>(smem_raw);
    cg::cluster_group cluster = cg::this_cluster();
    const int rank = (int)cluster.block_rank();
    const int tpl  = blockIdx.x / NC;
    const int tid  = threadIdx.x;
    const int wid  = tid >> 5, lane = tid & 31;
    const int r0   = rank * RPC;
    const float P  = 1.0f / (float)NN;
    const float alpha = 1.0f / (1.0f + expf(-a0[0]));
    const float oma = 1.0f - alpha, ta = 2.0f * alpha;
    int par = 0;

    // ---- phase 0: per-template small data ----
    for (int i = tid; i < MM * FF; i += TPB) s->F2[i] = tF[(size_t)tpl * MM * FF + i];
    if (tid < MM * MM) s->C2[tid] = tA[tpl * MM * MM + tid];
    if (tid == 0) {
        float qq[MM]; float mx = -1e30f;
        #pragma unroll
        for (int k = 0; k < MM; k++) { qq[k] = q0[tpl * MM + k]; mx = fmaxf(mx, qq[k]); }
        float ssum = 0.f;
        #pragma unroll
        for (int k = 0; k < MM; k++) { qq[k] = expf(qq[k] - mx); ssum += qq[k]; }
        #pragma unroll
        for (int k = 0; k < MM; k++) s->q[k] = qq[k] / ssum;
    }
    __syncthreads();
    if (tid < MM) {
        int j = tid;
        float a1 = 0.f, a2 = 0.f, a3 = 0.f;
        #pragma unroll
        for (int k = 0; k < MM; k++) {
            a1 += s->q[k] * s->C2[k * MM + j];
            float cj = s->C2[j * MM + k];
            a2 += cj * cj * s->q[k];
        }
        for (int c = 0; c < FF; c++) { float fv = s->F2[j * FF + c]; a3 += fv * fv; }
        s->qC2[j] = a1; s->cc[j] = a2; s->fsq[j] = a3;
    }
    __syncthreads();

    // ---- phase 1: M (feature cost), DegN, T0 = p q^T, ATC0 (closed form) ----
    for (int r = wid; r < RPC; r += NWARP) {
        int gi = r0 + r;
        const float* xr = x + (size_t)gi * FF;
        float acc[MM];
        #pragma unroll
        for (int j = 0; j < MM; j++) acc[j] = 0.f;
        float xs = 0.f;
        #pragma unroll
        for (int c = 0; c < FF / 32; c++) {
            float xv = xr[c * 32 + lane];
            xs += xv * xv;
            #pragma unroll
            for (int j = 0; j < MM; j++) acc[j] += xv * s->F2[j * FF + c * 32 + lane];
        }
        #pragma unroll
        for (int o = 16; o; o >>= 1) {
            xs += __shfl_xor_sync(0xffffffffu, xs, o);
            #pragma unroll
            for (int j = 0; j < MM; j++) acc[j] += __shfl_xor_sync(0xffffffffu, acc[j], o);
        }
        float dn = (float)g_deg[gi] * P;
        if (lane == 0) s->DegN[r] = dn;
        if (lane < MM) {
            int j = lane;
            s->M[r * SR + j]   = xs + s->fsq[j] - 2.f * acc[j];
            s->T[r * SR + j]   = P * s->q[j];
            s->ATC[r * SR + j] = dn * s->qC2[j];
        }
    }
    __syncthreads();

    // ---- Frank-Wolfe loop ----
    for (int fw = 0; fw < NFW; fw++) {
        // (a) G = (1-a)M + 2a(constC - 2 ATC); stats: sum|G|, min G
        float psum = 0.f, pmin = 1e30f;
        for (int li = tid; li < RPC; li += TPB) {
            float dn = s->DegN[li];
            #pragma unroll
            for (int j = 0; j < MM; j++) {
                int e = li * SR + j;
                float g = oma * s->M[e] + ta * (dn + s->cc[j] - 2.f * s->ATC[e]);
                s->K[e] = g;
                psum += fabsf(g);
                pmin = fminf(pmin, g);
            }
        }
        #pragma unroll
        for (int o = 16; o; o >>= 1) {
            psum += __shfl_xor_sync(0xffffffffu, psum, o);
            pmin = fminf(pmin, __shfl_xor_sync(0xffffffffu, pmin, o));
        }
        if (lane == 0) { s->Wred[wid][0] = psum; s->Wred[wid][1] = pmin; }
        __syncthreads();
        if (tid == 0) {
            float bs = 0.f, bm = 1e30f;
            for (int w = 0; w < NWARP; w++) { bs += s->Wred[w][0]; bm = fminf(bm, s->Wred[w][1]); }
            s->Pub[par][0] = bs; s->Pub[par][1] = bm;
        }
        cluster.sync();
        if (tid == 0) {
            float bs = 0.f, bm = 1e30f;
            for (int r = 0; r < NC; r++) {
                const float* rp = cluster.map_shared_rank(&s->Pub[0][0], r);
                bs += rp[par * 16 + 0];
                bm = fminf(bm, rp[par * 16 + 1]);
            }
            s->Scal[0] = 0.05f * (bs / (float)(NN * MM)) + 1e-9f;  // reg
            s->Scal[1] = bm;                                        // cmin
        }
        if (tid < MM) s->V[tid] = 1.f;   // reset Sinkhorn scaling (g=0)
        par ^= 1;
        __syncthreads();

        // (b) K = exp(-(G - cmin)/reg)  (exact shift invariance)
        {
            float reg = s->Scal[0], cmin = s->Scal[1];
            float inv = 1.0f / reg;
            for (int li = tid; li < RPC; li += TPB) {
                #pragma unroll
                for (int j = 0; j < MM; j++) {
                    int e = li * SR + j;
                    s->K[e] = expf(fmaxf((cmin - s->K[e]) * inv, -80.f));
                }
            }
        }

        // (c) Sinkhorn: u = p/(Kv); v = q/(K^T u); one cluster.sync per iter
        for (int it = 0; it < NSINK; it++) {
            float vr[MM];
            #pragma unroll
            for (int j = 0; j < MM; j++) vr[j] = s->V[j];
            float col[MM];
            #pragma unroll
            for (int j = 0; j < MM; j++) col[j] = 0.f;
            for (int li = tid; li < RPC; li += TPB) {
                float kr[MM];
                #pragma unroll
                for (int j = 0; j < MM; j++) kr[j] = s->K[li * SR + j];
                float kv = 0.f;
                #pragma unroll
                for (int j = 0; j < MM; j++) kv += kr[j] * vr[j];
                float u = P / kv;
                s->U[li] = u;
                #pragma unroll
                for (int j = 0; j < MM; j++) col[j] += kr[j] * u;
            }
            #pragma unroll
            for (int o = 16; o; o >>= 1) {
                #pragma unroll
                for (int j = 0; j < MM; j++) col[j] += __shfl_xor_sync(0xffffffffu, col[j], o);
            }
            if (lane == 0) {
                #pragma unroll
                for (int j = 0; j < MM; j++) s->Wred[wid][j] = col[j];
            }
            __syncthreads();
            if (tid < MM) {
                float t = 0.f;
                for (int w = 0; w < NWARP; w++) t += s->Wred[w][tid];
                s->Pub[par][tid] = t;
            }
            cluster.sync();
            if (tid < MM) {
                float tot = 0.f;
                for (int r = 0; r < NC; r++) {
                    const float* rp = cluster.map_shared_rank(&s->Pub[0][0], r);
                    tot += rp[par * 16 + tid];
                }
                s->V[tid] = s->q[tid] / tot;
            }
            par ^= 1;
            __syncthreads();
        }

        // (d) dT = u.K.v - T; Y = dT@C2 -> global; partial dots for b
        float pM = 0.f, pC = 0.f, pA = 0.f;
        {
            float vr[MM];
            #pragma unroll
            for (int j = 0; j < MM; j++) vr[j] = s->V[j];
            for (int li = tid; li < RPC; li += TPB) {
                float u = s->U[li];
                float d[MM];
                #pragma unroll
                for (int j = 0; j < MM; j++) {
                    int e = li * SR + j;
                    d[j] = u * s->K[e] * vr[j] - s->T[e];
                }
                float dn = s->DegN[li];
                #pragma unroll
                for (int j = 0; j < MM; j++) {
                    int e = li * SR + j;
                    pM += s->M[e] * d[j];
                    pC += (dn + s->cc[j]) * d[j];
                    pA += s->ATC[e] * d[j];
                }
                float* yp = g_Y + ((size_t)tpl * NN + (r0 + li)) * MM;
                #pragma unroll
                for (int jj = 0; jj < MM; jj++) {
                    float y = 0.f;
                    #pragma unroll
                    for (int j = 0; j < MM; j++) y += d[j] * s->C2[j * MM + jj];
                    yp[jj] = y;
                }
            }
        }
        __threadfence();
        cluster.sync();

        // (e) SpMM: AdTC = A @ Y (CSR, deduped, sorted -> deterministic); pa
        float pa = 0.f;
        {
            float vr[MM];
            #pragma unroll
            for (int j = 0; j < MM; j++) vr[j] = s->V[j];
            for (int li = tid; li < RPC; li += TPB) {
                int gi = r0 + li;
                int b = g_rowptr[gi], en = g_rowptr[gi + 1];
                float acc[MM];
                #pragma unroll
                for (int j = 0; j < MM; j++) acc[j] = 0.f;
                for (int p2 = b; p2 < en; p2++) {
                    int col = g_cols[p2];
                    const float2* yp = reinterpret_cast<const float2*>(
                        g_Y + ((size_t)tpl * NN + col) * MM);
                    float2 v0 = __ldg(yp + 0), v1 = __ldg(yp + 1), v2 = __ldg(yp + 2),
                           v3 = __ldg(yp + 3), v4 = __ldg(yp + 4);
                    acc[0] += v0.x; acc[1] += v0.y;
                    acc[2] += v1.x; acc[3] += v1.y;
                    acc[4] += v2.x; acc[5] += v2.y;
                    acc[6] += v3.x; acc[7] += v3.y;
                    acc[8] += v4.x; acc[9] += v4.y;
                }
                float u = s->U[li];
                #pragma unroll
                for (int j = 0; j < MM; j++) {
                    int e = li * SR + j;
                    s->AdT[e] = acc[j];
                    float d = u * s->K[e] * vr[j] - s->T[e];
                    pa += acc[j] * d;
                }
            }
        }

        // (f) reduce (pa, pM, pC, pA) block+cluster; compute gamma
        #pragma unroll
        for (int o = 16; o; o >>= 1) {
            pa += __shfl_xor_sync(0xffffffffu, pa, o);
            pM += __shfl_xor_sync(0xffffffffu, pM, o);
            pC += __shfl_xor_sync(0xffffffffu, pC, o);
            pA += __shfl_xor_sync(0xffffffffu, pA, o);
        }
        if (lane == 0) {
            s->Wred[wid][0] = pa; s->Wred[wid][1] = pM;
            s->Wred[wid][2] = pC; s->Wred[wid][3] = pA;
        }
        __syncthreads();
        if (tid == 0) {
            float t0 = 0, t1 = 0, t2 = 0, t3 = 0;
            for (int w = 0; w < NWARP; w++) {
                t0 += s->Wred[w][0]; t1 += s->Wred[w][1];
                t2 += s->Wred[w][2]; t3 += s->Wred[w][3];
            }
            s->Pub[par][0] = t0; s->Pub[par][1] = t1;
            s->Pub[par][2] = t2; s->Pub[par][3] = t3;
        }
        cluster.sync();
        if (tid == 0) {
            float Ta = 0, Tm = 0, Tc = 0, TA = 0;
            for (int r = 0; r < NC; r++) {
                const float* rp = cluster.map_shared_rank(&s->Pub[0][0], r);
                Ta += rp[par * 16 + 0]; Tm += rp[par * 16 + 1];
                Tc += rp[par * 16 + 2]; TA += rp[par * 16 + 3];
            }
            float a = -2.f * alpha * Ta;
            float b = oma * Tm + alpha * (Tc - 4.f * TA);
            float gam;
            if (a > 0.f) {
                gam = -b / (2.f * a + 1e-16f);
                gam = fminf(fmaxf(gam, 0.f), 1.f);
            } else {
                gam = (a + b < 0.f) ? 1.f : 0.f;
            }
            s->Scal[2] = gam;
        }
        par ^= 1;
        __syncthreads();

        // (g) T += gam*dT; ATC += gam*AdTC
        {
            float gam = s->Scal[2];
            float vr[MM];
            #pragma unroll
            for (int j = 0; j < MM; j++) vr[j] = s->V[j];
            for (int li = tid; li < RPC; li += TPB) {
                float u = s->U[li];
                #pragma unroll
                for (int j = 0; j < MM; j++) {
                    int e = li * SR + j;
                    float d = u * s->K[e] * vr[j] - s->T[e];
                    s->T[e]   += gam * d;
                    s->ATC[e] += gam * s->AdT[e];
                }
            }
        }
        __syncthreads();
    }

    // ---- final FGW distance ----
    float pd = 0.f;
    for (int li = tid; li < RPC; li += TPB) {
        float dn = s->DegN[li];
        #pragma unroll
        for (int j = 0; j < MM; j++) {
            int e = li * SR + j;
            float t = s->T[e];
            pd += oma * s->M[e] * t + alpha * ((dn + s->cc[j]) * t - 2.f * s->ATC[e] * t);
        }
    }
    #pragma unroll
    for (int o = 16; o; o >>= 1) pd += __shfl_xor_sync(0xffffffffu, pd, o);
    if (lane == 0) s->Wred[wid][0] = pd;
    __syncthreads();
    if (tid == 0) {
        float bs = 0.f;
        for (int w = 0; w < NWARP; w++) bs += s->Wred[w][0];
        s->Pub[par][0] = bs;
    }
    cluster.sync();
    if (rank == 0 && tid == 0) {
        float tot = 0.f;
        for (int r = 0; r < NC; r++) {
            const float* rp = cluster.map_shared_rank(&s->Pub[0][0], r);
            tot += rp[par * 16 + 0];
        }
        out[tpl] = tot;
    }
    cluster.sync();  // keep all CTAs alive until DSMEM reads complete
}

// ---------------- launch ----------------
extern "C" void kernel_launch(void* const* d_in, const int* in_sizes, int n_in,
                              void* d_out, int out_size)
{
    const float* x  = (const float*)d_in[0];
    const int*   ei = (const int*)  d_in[1];
    const float* tA = (const float*)d_in[2];
    const float* tF = (const float*)d_in[3];
    const float* q0 = (const float*)d_in[4];
    const float* a0 = (const float*)d_in[5];
    float* out = (float*)d_out;
    int E = in_sizes[1] / 2;

    cudaFuncSetAttribute(k_main, cudaFuncAttributeMaxDynamicSharedMemorySize,
                         (int)sizeof(Smem));

    k_mark<<<(E + 255) / 256, 256>>>(ei, E);
    k_deg<<<(NN * 32 + 255) / 256, 256>>>();
    k_scan<<<1, 1024>>>();
    k_fill<<<(NN * 32 + 255) / 256, 256>>>();
    k_main<<<NT * NC, TPB, sizeof(Smem)>>>(x, tA, tF, q0, a0, out);
}